// round 3
// baseline (speedup 1.0000x reference)
#include <cuda_runtime.h>
#include <math.h>

#define B   32
#define E   512
#define H   512
#define H4  2048
#define S   64
#define T   48
#define VT  32000
#define TL  (T-1)      // 47 output steps
#define VB  640        // vocab rows per logits block
#define NCHUNK (VT/VB) // 50

// ---------------- device scratch (no allocations allowed) ----------------
__device__ __align__(128) float g_x[S*E*B];
__device__ __align__(128) float g_y[T*E*B];
__device__ __align__(128) float g_zx0[S*H4*B];
__device__ __align__(128) float g_zx1[S*H4*B];
__device__ __align__(128) float g_zy [T*H4*B];
__device__ __align__(128) float g_h1seq[S*H*B];
__device__ __align__(128) float g_h2seq[S*H*B];
__device__ __align__(128) float g_ebsh[B*S*H];   // encode_h as [b,s,h]
__device__ __align__(128) float g_ebhs[B*H*S];   // encode_h as [b,h,s]
__device__ __align__(128) float g_c0[H*B];
__device__ __align__(128) float g_c1[H*B];
__device__ __align__(128) float g_dh0a[H*B];
__device__ __align__(128) float g_dh0b[H*B];
__device__ __align__(128) float g_dh1a[H*B];
__device__ __align__(128) float g_dh1b[H*B];
__device__ __align__(128) float g_ct[H*B];
__device__ __align__(128) float g_tmp[H*B];
__device__ __align__(128) float g_zero[H*B];
__device__ __align__(128) float g_decout[T*H*B];
__device__ __align__(128) float g_pmax[TL*NCHUNK*B];
__device__ __align__(128) float g_psum[TL*NCHUNK*B];
__device__ __align__(128) float g_tgtl[TL*B];
__device__ __align__(128) float g_lp[TL*B];

// ---------------- small helpers ----------------
__global__ void k_zero(float* __restrict__ p, int n) {
    int i = blockIdx.x * 256 + threadIdx.x;
    if (i < n) p[i] = 0.f;
}

// out[n,e,b] = emb[idx[n,b]*E + e]   (layout [n][e][b])
__global__ void k_embed(const int* __restrict__ idx, const float* __restrict__ emb,
                        float* __restrict__ dst) {
    int n = blockIdx.x, b = blockIdx.y;
    int row = idx[n * B + b];
    const float* src = emb + (size_t)row * E;
    float* d = dst + (size_t)n * E * B + b;
    for (int e = threadIdx.x; e < E; e += blockDim.x) d[(size_t)e * B] = src[e];
}

// Z[n,o,b] = bias[o] + sum_{k<512} W[o*ldw+k] * U[(n*512+k)*B+b]
// grid (32, N), 256 threads, 8 warps x 8 rows = 64 rows per block.
__global__ void __launch_bounds__(256) k_gemm_pre(
        const float* __restrict__ W, int ldw, const float* __restrict__ bias,
        const float* __restrict__ U, float* __restrict__ Z) {
    __shared__ __align__(16) float su[128 * B];
    const int tid = threadIdx.x, lane = tid & 31, warp = tid >> 5;
    const int n = blockIdx.y;
    const int o0 = blockIdx.x * 64 + warp * 8;
    float acc[8] = {0.f,0.f,0.f,0.f,0.f,0.f,0.f,0.f};
    const float* Ub = U + (size_t)n * 512 * B;
    for (int k0 = 0; k0 < 512; k0 += 128) {
        const float4* srcv = (const float4*)(Ub + (size_t)k0 * B);
        float4* dv = (float4*)su;
        #pragma unroll
        for (int i = tid; i < 128 * B / 4; i += 256) dv[i] = srcv[i];
        __syncthreads();
        #pragma unroll 8
        for (int kk = 0; kk < 128; kk += 4) {
            float u0 = su[(kk+0)*B + lane], u1 = su[(kk+1)*B + lane];
            float u2 = su[(kk+2)*B + lane], u3 = su[(kk+3)*B + lane];
            #pragma unroll
            for (int r = 0; r < 8; r++) {
                float4 w = *(const float4*)(W + (size_t)(o0 + r) * ldw + k0 + kk);
                acc[r] = fmaf(w.x,u0,fmaf(w.y,u1,fmaf(w.z,u2,fmaf(w.w,u3,acc[r]))));
            }
        }
        __syncthreads();
    }
    #pragma unroll
    for (int r = 0; r < 8; r++)
        Z[((size_t)n * H4 + o0 + r) * B + lane] = acc[r] + bias[o0 + r];
}

// Fused LSTM cell step. Block owns 4 h-indices x 4 gates (16 rows).
// z[o,b] = (zpre ? zpre[o,b] : bias[o]) + W1[o,:] . u1[:,b] + W2[o,:] . u2[:,b]
// then gate math, in-place c update, h written to Hout. grid 128, 256 thr.
__global__ void __launch_bounds__(256) k_cell(
        const float* __restrict__ zpre, const float* __restrict__ bias,
        const float* __restrict__ W1, int ldw1, const float* __restrict__ u1,
        const float* __restrict__ W2, int ldw2, const float* __restrict__ u2,
        float* __restrict__ C, float* __restrict__ Hout) {
    __shared__ __align__(16) float su[128 * B];
    __shared__ float sz[16 * B];
    const int tid = threadIdx.x, lane = tid & 31, warp = tid >> 5;
    const int h0 = blockIdx.x * 4;
    int o[2]; float acc[2];
    #pragma unroll
    for (int rr = 0; rr < 2; rr++) {
        int r = warp * 2 + rr;
        o[rr] = (r >> 2) * H + h0 + (r & 3);
        acc[rr] = zpre ? zpre[(size_t)o[rr] * B + lane] : bias[o[rr]];
    }
    for (int m = 0; m < 2; m++) {
        const float* W = m ? W2 : W1;
        const float* u = m ? u2 : u1;
        const int ldw   = m ? ldw2 : ldw1;
        if (!W) continue;
        for (int k0 = 0; k0 < H; k0 += 128) {
            const float4* srcv = (const float4*)(u + (size_t)k0 * B);
            float4* dv = (float4*)su;
            #pragma unroll
            for (int i = tid; i < 128 * B / 4; i += 256) dv[i] = srcv[i];
            __syncthreads();
            #pragma unroll 8
            for (int kk = 0; kk < 128; kk += 4) {
                float u0 = su[(kk+0)*B + lane], u1v = su[(kk+1)*B + lane];
                float u2v = su[(kk+2)*B + lane], u3v = su[(kk+3)*B + lane];
                #pragma unroll
                for (int rr = 0; rr < 2; rr++) {
                    float4 w = *(const float4*)(W + (size_t)o[rr] * ldw + k0 + kk);
                    acc[rr] = fmaf(w.x,u0,fmaf(w.y,u1v,fmaf(w.z,u2v,fmaf(w.w,u3v,acc[rr]))));
                }
            }
            __syncthreads();
        }
    }
    #pragma unroll
    for (int rr = 0; rr < 2; rr++) sz[(warp * 2 + rr) * B + lane] = acc[rr];
    __syncthreads();
    if (tid < 4 * B) {
        int j = tid >> 5, b = tid & 31;
        float zi = sz[(0*4 + j) * B + b];
        float zf = sz[(1*4 + j) * B + b];
        float zg = sz[(2*4 + j) * B + b];
        float zo = sz[(3*4 + j) * B + b];
        float ig = 1.f / (1.f + expf(-zi));
        float fg = 1.f / (1.f + expf(-zf));
        float gg = tanhf(zg);
        float og = 1.f / (1.f + expf(-zo));
        int h = h0 + j;
        float c  = C[h * B + b];
        float c2 = fg * c + ig * gg;
        C[h * B + b]    = c2;
        Hout[h * B + b] = og * tanhf(c2);
    }
}

// out[o,b] = tanh( W1[o,:] . u1 (+ W2[o,:] . u2) ),  512 rows, K=512 per mat.
// grid 64, 256 threads, 8 warps x 1 row.
__global__ void __launch_bounds__(256) k_gemm_tanh(
        const float* __restrict__ W1, int ldw1, const float* __restrict__ u1,
        const float* __restrict__ W2, int ldw2, const float* __restrict__ u2,
        float* __restrict__ out) {
    __shared__ __align__(16) float su[128 * B];
    const int tid = threadIdx.x, lane = tid & 31, warp = tid >> 5;
    const int o = blockIdx.x * 8 + warp;
    float acc = 0.f;
    for (int m = 0; m < 2; m++) {
        const float* W = m ? W2 : W1;
        const float* u = m ? u2 : u1;
        const int ldw = m ? ldw2 : ldw1;
        if (!W) continue;
        for (int k0 = 0; k0 < H; k0 += 128) {
            const float4* srcv = (const float4*)(u + (size_t)k0 * B);
            float4* dv = (float4*)su;
            #pragma unroll
            for (int i = tid; i < 128 * B / 4; i += 256) dv[i] = srcv[i];
            __syncthreads();
            #pragma unroll 8
            for (int kk = 0; kk < 128; kk += 4) {
                float4 w = *(const float4*)(W + (size_t)o * ldw + k0 + kk);
                acc = fmaf(w.x, su[(kk+0)*B+lane],
                      fmaf(w.y, su[(kk+1)*B+lane],
                      fmaf(w.z, su[(kk+2)*B+lane],
                      fmaf(w.w, su[(kk+3)*B+lane], acc))));
            }
            __syncthreads();
        }
    }
    out[(size_t)o * B + lane] = tanhf(acc);
}

// encode_h [s,h,b] -> [b,s,h] and [b,h,s]
__global__ void k_transpose() {
    int s = blockIdx.x, b = blockIdx.y;
    for (int h = threadIdx.x; h < H; h += blockDim.x) {
        float v = g_h2seq[((size_t)s * H + h) * B + b];
        g_ebsh[((size_t)b * S + s) * H + h] = v;
        g_ebhs[((size_t)b * H + h) * S + s] = v;
    }
}

// attention for one decoder step: pt, scores, softmax*gauss, ct. grid 32 (b), 128 thr.
__global__ void __launch_bounds__(128) k_attn(const float* __restrict__ yt,
                                              const int* __restrict__ elen_p,
                                              const float* __restrict__ Wpt) {
    __shared__ float s_yt[H];
    __shared__ float s_at[S];
    __shared__ float s_red[4];
    __shared__ float s_pt;
    const int b = blockIdx.x, tid = threadIdx.x, lane = tid & 31, warp = tid >> 5;
    float p = 0.f;
    for (int h = tid; h < H; h += 128) {
        float v = yt[(size_t)h * B + b];
        s_yt[h] = v;
        p += g_tmp[(size_t)h * B + b] * Wpt[h];
    }
    #pragma unroll
    for (int off = 16; off; off >>= 1) p += __shfl_xor_sync(0xffffffffu, p, off);
    if (lane == 0) s_red[warp] = p;
    __syncthreads();
    if (tid == 0) {
        float t = s_red[0] + s_red[1] + s_red[2] + s_red[3];
        s_pt = (1.f / (1.f + expf(-t))) * (float)elen_p[b];
    }
    __syncthreads();
    const float pt = s_pt;
    const int el = elen_p[b];
    for (int s = warp; s < S; s += 4) {
        const float* eh = &g_ebsh[((size_t)b * S + s) * H];
        float v = 0.f;
        for (int h = lane; h < H; h += 32) v += s_yt[h] * eh[h];
        #pragma unroll
        for (int off = 16; off; off >>= 1) v += __shfl_xor_sync(0xffffffffu, v, off);
        if (lane == 0) s_at[s] = (s < el) ? v : -INFINITY;
    }
    __syncthreads();
    if (warp == 0) {
        float v0 = s_at[lane], v1 = s_at[lane + 32];
        float m = fmaxf(v0, v1);
        #pragma unroll
        for (int off = 16; off; off >>= 1) m = fmaxf(m, __shfl_xor_sync(0xffffffffu, m, off));
        float e0 = expf(v0 - m), e1 = expf(v1 - m);
        float sm = e0 + e1;
        #pragma unroll
        for (int off = 16; off; off >>= 1) sm += __shfl_xor_sync(0xffffffffu, sm, off);
        float inv = 1.f / sm;
        float d0 = (float)lane - pt, d1 = (float)(lane + 32) - pt;
        s_at[lane]      = e0 * inv * expf(-d0 * d0 * (1.f / 50.f));
        s_at[lane + 32] = e1 * inv * expf(-d1 * d1 * (1.f / 50.f));
    }
    __syncthreads();
    for (int h = warp; h < H; h += 4) {
        const float* eh = &g_ebhs[((size_t)b * H + h) * S];
        float v = s_at[lane] * eh[lane] + s_at[lane + 32] * eh[lane + 32];
        #pragma unroll
        for (int off = 16; off; off >>= 1) v += __shfl_xor_sync(0xffffffffu, v, off);
        if (lane == 0) g_ct[(size_t)h * B + b] = v;
    }
}

// vocab projection + online logsumexp partials + target-logit grab.
// grid (NCHUNK, TL), 256 thr, dynamic smem = 512*32*4 = 64KB decoder-state tile.
__global__ void __launch_bounds__(256) k_logits(const float* __restrict__ Wf,
                                                const int* __restrict__ target) {
    extern __shared__ __align__(16) float sdec[]; // [512][32]
    __shared__ float rm[8][32], rs[8][32];
    const int t = blockIdx.y, c = blockIdx.x;
    const int tid = threadIdx.x, lane = tid & 31, warp = tid >> 5;
    const float4* src = (const float4*)&g_decout[(size_t)t * H * B];
    float4* dv = (float4*)sdec;
    #pragma unroll
    for (int i = tid; i < H * B / 4; i += 256) dv[i] = src[i];
    __syncthreads();
    const int tgt = target[(t + 1) * B + lane];
    float m = -INFINITY, ss = 0.f;
    for (int pass = 0; pass < 10; pass++) {
        const int v0 = c * VB + warp * 80 + pass * 8;
        float acc[8] = {0.f,0.f,0.f,0.f,0.f,0.f,0.f,0.f};
        #pragma unroll 2
        for (int k0 = 0; k0 < H; k0 += 4) {
            float u0 = sdec[(k0+0)*B + lane], u1 = sdec[(k0+1)*B + lane];
            float u2 = sdec[(k0+2)*B + lane], u3 = sdec[(k0+3)*B + lane];
            #pragma unroll
            for (int r = 0; r < 8; r++) {
                float4 w = *(const float4*)(Wf + (size_t)(v0 + r) * H + k0);
                acc[r] = fmaf(w.x,u0,fmaf(w.y,u1,fmaf(w.z,u2,fmaf(w.w,u3,acc[r]))));
            }
        }
        #pragma unroll
        for (int r = 0; r < 8; r++) {
            float x = acc[r];
            if (v0 + r == tgt) g_tgtl[t * B + lane] = x;
            float nm = fmaxf(m, x);
            ss = ss * expf(m - nm) + expf(x - nm);
            m = nm;
        }
    }
    rm[warp][lane] = m; rs[warp][lane] = ss;
    __syncthreads();
    if (tid < 32) {
        float M = -INFINITY, SS = 0.f;
        #pragma unroll
        for (int w = 0; w < 8; w++) {
            float wm = rm[w][tid], wss = rs[w][tid];
            float nm = fmaxf(M, wm);
            SS = SS * expf(M - nm) + wss * expf(wm - nm);
            M = nm;
        }
        g_pmax[((size_t)t * NCHUNK + c) * B + tid] = M;
        g_psum[((size_t)t * NCHUNK + c) * B + tid] = SS;
    }
}

__global__ void k_combine(const int* __restrict__ target) {
    const int t = blockIdx.x, b = threadIdx.x;
    float M = -INFINITY;
    for (int c = 0; c < NCHUNK; c++)
        M = fmaxf(M, g_pmax[((size_t)t * NCHUNK + c) * B + b]);
    float ss = 0.f;
    for (int c = 0; c < NCHUNK; c++)
        ss += g_psum[((size_t)t * NCHUNK + c) * B + b] *
              expf(g_pmax[((size_t)t * NCHUNK + c) * B + b] - M);
    float lse = M + logf(ss);
    float mask = (target[(t + 1) * B + b] != 0) ? 1.f : 0.f;
    g_lp[t * B + b] = mask * (g_tgtl[t * B + b] - lse);
}

__global__ void k_out(float* __restrict__ out) {
    const int b = threadIdx.x;
    float s = 0.f;
    for (int t = 0; t < TL; t++) s += g_lp[t * B + b];
    out[b] = s;
}

// ---------------- host ----------------
extern "C" void kernel_launch(void* const* d_in, const int* in_sizes, int n_in,
                              void* d_out, int out_size) {
    const int*   source   = (const int*)d_in[0];
    const int*   target   = (const int*)d_in[1];
    const int*   elen     = (const int*)d_in[2];
    const float* src_emb  = (const float*)d_in[3];
    const float* tar_emb  = (const float*)d_in[4];
    const float* eWih0    = (const float*)d_in[5];
    const float* eWhh0    = (const float*)d_in[6];
    const float* eb0      = (const float*)d_in[7];
    const float* eWih1    = (const float*)d_in[8];
    const float* eWhh1    = (const float*)d_in[9];
    const float* eb1      = (const float*)d_in[10];
    const float* dWih0    = (const float*)d_in[11];
    const float* dWhh0    = (const float*)d_in[12];
    const float* db0      = (const float*)d_in[13];
    const float* dWih1    = (const float*)d_in[14];
    const float* dWhh1    = (const float*)d_in[15];
    const float* db1      = (const float*)d_in[16];
    const float* W_ht2tan = (const float*)d_in[17];
    const float* W_tan2pt = (const float*)d_in[18];
    const float* W_ct2ht  = (const float*)d_in[19];
    const float* W_final  = (const float*)d_in[20];
    float* out = (float*)d_out;

    float *x,*y,*zx0,*zx1,*zy,*h1seq,*h2seq,*c0,*c1;
    float *dh0a,*dh0b,*dh1a,*dh1b,*ct,*tmp,*zerop,*decout;
    cudaGetSymbolAddress((void**)&x, g_x);
    cudaGetSymbolAddress((void**)&y, g_y);
    cudaGetSymbolAddress((void**)&zx0, g_zx0);
    cudaGetSymbolAddress((void**)&zx1, g_zx1);
    cudaGetSymbolAddress((void**)&zy, g_zy);
    cudaGetSymbolAddress((void**)&h1seq, g_h1seq);
    cudaGetSymbolAddress((void**)&h2seq, g_h2seq);
    cudaGetSymbolAddress((void**)&c0, g_c0);
    cudaGetSymbolAddress((void**)&c1, g_c1);
    cudaGetSymbolAddress((void**)&dh0a, g_dh0a);
    cudaGetSymbolAddress((void**)&dh0b, g_dh0b);
    cudaGetSymbolAddress((void**)&dh1a, g_dh1a);
    cudaGetSymbolAddress((void**)&dh1b, g_dh1b);
    cudaGetSymbolAddress((void**)&ct, g_ct);
    cudaGetSymbolAddress((void**)&tmp, g_tmp);
    cudaGetSymbolAddress((void**)&zerop, g_zero);
    cudaGetSymbolAddress((void**)&decout, g_decout);

    cudaFuncSetAttribute(k_logits, cudaFuncAttributeMaxDynamicSharedMemorySize, 65536);

    const int nzb = (H * B + 255) / 256;
    k_zero<<<nzb, 256>>>(zerop, H * B);
    k_zero<<<nzb, 256>>>(c0, H * B);
    k_zero<<<nzb, 256>>>(c1, H * B);

    k_embed<<<dim3(S, B), 128>>>(source, src_emb, x);
    k_embed<<<dim3(T, B), 128>>>(target, tar_emb, y);

    // encoder layer 0
    k_gemm_pre<<<dim3(32, S), 256>>>(eWih0, E, eb0, x, zx0);
    for (int s = 0; s < S; s++) {
        const float* hp = s ? h1seq + (size_t)(s - 1) * H * B : zerop;
        k_cell<<<128, 256>>>(zx0 + (size_t)s * H4 * B, nullptr,
                             eWhh0, H, hp, nullptr, 0, nullptr,
                             c0, h1seq + (size_t)s * H * B);
    }
    // encoder layer 1
    k_gemm_pre<<<dim3(32, S), 256>>>(eWih1, H, eb1, h1seq, zx1);
    for (int s = 0; s < S; s++) {
        const float* hp = s ? h2seq + (size_t)(s - 1) * H * B : zerop;
        k_cell<<<128, 256>>>(zx1 + (size_t)s * H4 * B, nullptr,
                             eWhh1, H, hp, nullptr, 0, nullptr,
                             c1, h2seq + (size_t)s * H * B);
    }
    k_transpose<<<dim3(S, B), 128>>>();

    // decoder: precompute y contribution to layer-0 gates
    k_gemm_pre<<<dim3(32, T), 256>>>(dWih0, E + H, db0, y, zy);

    for (int t = 0; t < T; t++) {
        const float* htp = t ? decout + (size_t)(t - 1) * H * B : zerop;
        const float* h0p = t ? (((t - 1) & 1) ? dh0b : dh0a)
                             : h1seq + (size_t)(S - 1) * H * B;
        float* h0c = (t & 1) ? dh0b : dh0a;
        k_cell<<<128, 256>>>(zy + (size_t)t * H4 * B, nullptr,
                             dWih0 + E, E + H, htp,
                             dWhh0, H, h0p, c0, h0c);
        const float* h1p = t ? (((t - 1) & 1) ? dh1b : dh1a)
                             : h2seq + (size_t)(S - 1) * H * B;
        float* h1c = (t & 1) ? dh1b : dh1a;
        k_cell<<<128, 256>>>(nullptr, db1,
                             dWih1, H, h0c,
                             dWhh1, H, h1p, c1, h1c);
        k_gemm_tanh<<<64, 256>>>(W_ht2tan, H, h1c, nullptr, 0, nullptr, tmp);
        k_attn<<<32, 128>>>(h1c, elen, W_tan2pt);
        k_gemm_tanh<<<64, 256>>>(W_ct2ht, 2 * H, ct, W_ct2ht + H, 2 * H, h1c,
                                 decout + (size_t)t * H * B);
    }

    k_logits<<<dim3(NCHUNK, TL), 256, 65536>>>(W_final, target);
    k_combine<<<TL, 32>>>(target);
    k_out<<<1, 32>>>(out);
}

// round 4
// speedup vs baseline: 1.1358x; 1.1358x over previous
#include <cuda_runtime.h>
#include <math.h>

#define B   32
#define E   512
#define H   512
#define H4  2048
#define S   64
#define T   48
#define VT  32000
#define TL  (T-1)      // 47 output steps
#define VB  640        // vocab rows per logits block
#define NCHUNK (VT/VB) // 50
#define NBLK 128       // persistent grid size (<= 148 SMs -> all co-resident)

// ---------------- device scratch (no allocations allowed) ----------------
__device__ __align__(128) float g_x[S*E*B];
__device__ __align__(128) float g_y[T*E*B];
__device__ __align__(128) float g_zx0[S*H4*B];
__device__ __align__(128) float g_zy [T*H4*B];
__device__ __align__(128) float g_h1seq[S*H*B];
__device__ __align__(128) float g_h2seq[S*H*B];
__device__ __align__(128) float g_ebsh[B*S*H];   // encode_h as [b,s,h]
__device__ __align__(128) float g_ebhs[B*H*S];   // encode_h as [b,h,s]
__device__ __align__(128) float g_c0[H*B];
__device__ __align__(128) float g_c1[H*B];
__device__ __align__(128) float g_dh0a[H*B];
__device__ __align__(128) float g_dh0b[H*B];
__device__ __align__(128) float g_dh1a[H*B];
__device__ __align__(128) float g_dh1b[H*B];
__device__ __align__(128) float g_ct[H*B];
__device__ __align__(128) float g_tmp[H*B];
__device__ __align__(128) float g_zero[H*B];
__device__ __align__(128) float g_scores[B*S];
__device__ __align__(128) float g_decout[T*H*B];
__device__ __align__(128) float g_pmax[TL*NCHUNK*B];
__device__ __align__(128) float g_psum[TL*NCHUNK*B];
__device__ __align__(128) float g_tgtl[TL*B];
__device__ __align__(128) float g_lp[TL*B];

// ---------------- packed fp32x2 FMA helpers (Blackwell FFMA2) ------------
__device__ __forceinline__ unsigned long long pack2(float lo, float hi) {
    unsigned long long r;
    asm("mov.b64 %0, {%1, %2};" : "=l"(r) : "f"(lo), "f"(hi));
    return r;
}
__device__ __forceinline__ void fma2(unsigned long long& a,
                                     unsigned long long w, unsigned long long u) {
    asm("fma.rn.f32x2 %0, %1, %2, %3;" : "=l"(a) : "l"(w), "l"(u), "l"(a));
}
__device__ __forceinline__ float sum2(unsigned long long v) {
    float lo, hi;
    asm("mov.b64 {%0, %1}, %2;" : "=f"(lo), "=f"(hi) : "l"(v));
    return lo + hi;
}

// ---------------- software grid barrier (all NBLK blocks co-resident) ----
__device__ unsigned g_cnt = 0;
__device__ volatile unsigned g_gen = 0;

__device__ __forceinline__ void gridbar() {
    __syncthreads();
    if (threadIdx.x == 0) {
        unsigned old = g_gen;
        __threadfence();
        unsigned a = atomicAdd(&g_cnt, 1u);
        if (a == NBLK - 1) {
            atomicExch(&g_cnt, 0u);
            __threadfence();
            g_gen = old + 1;
        } else {
            while (g_gen == old) __nanosleep(64);
        }
        __threadfence();
    }
    __syncthreads();
}

// ---------------- small helpers ----------------
__global__ void k_zero(float* __restrict__ p, int n) {
    int i = blockIdx.x * 256 + threadIdx.x;
    if (i < n) p[i] = 0.f;
}

// out[n,e,b] = emb[idx[n,b]*E + e]   (layout [n][e][b])
__global__ void k_embed(const int* __restrict__ idx, const float* __restrict__ emb,
                        float* __restrict__ dst) {
    int n = blockIdx.x, b = blockIdx.y;
    int row = idx[n * B + b];
    const float* src = emb + (size_t)row * E;
    float* d = dst + (size_t)n * E * B + b;
    for (int e = threadIdx.x; e < E; e += blockDim.x) d[(size_t)e * B] = src[e];
}

// Z[n,o,b] = bias[o] + sum_{k<512} W[o*ldw+k] * U[(n*512+k)*B+b]
// grid (32, N), 256 threads, 8 warps x 8 rows = 64 rows per block.
__global__ void __launch_bounds__(256) k_gemm_pre(
        const float* __restrict__ W, int ldw, const float* __restrict__ bias,
        const float* __restrict__ U, float* __restrict__ Z) {
    __shared__ __align__(16) float su[128 * B];
    const int tid = threadIdx.x, lane = tid & 31, warp = tid >> 5;
    const int n = blockIdx.y;
    const int o0 = blockIdx.x * 64 + warp * 8;
    unsigned long long acc2[8] = {0ull,0ull,0ull,0ull,0ull,0ull,0ull,0ull};
    const float* Ub = U + (size_t)n * 512 * B;
    for (int k0 = 0; k0 < 512; k0 += 128) {
        const float4* srcv = (const float4*)(Ub + (size_t)k0 * B);
        float4* dv = (float4*)su;
        #pragma unroll
        for (int i = tid; i < 128 * B / 4; i += 256) dv[i] = srcv[i];
        __syncthreads();
        #pragma unroll 8
        for (int kk = 0; kk < 128; kk += 4) {
            unsigned long long u01 = pack2(su[(kk+0)*B + lane], su[(kk+1)*B + lane]);
            unsigned long long u23 = pack2(su[(kk+2)*B + lane], su[(kk+3)*B + lane]);
            #pragma unroll
            for (int r = 0; r < 8; r++) {
                ulonglong2 w = *(const ulonglong2*)(W + (size_t)(o0 + r) * ldw + k0 + kk);
                fma2(acc2[r], w.x, u01);
                fma2(acc2[r], w.y, u23);
            }
        }
        __syncthreads();
    }
    #pragma unroll
    for (int r = 0; r < 8; r++)
        Z[((size_t)n * H4 + o0 + r) * B + lane] = sum2(acc2[r]) + bias[o0 + r];
}

// ---------------- fused LSTM cell chunk (device fn, block owns 16 rows) ----
__device__ __forceinline__ void cell_chunk(
        int blk, float* su, float* sz,
        const float* __restrict__ zpre, const float* __restrict__ bias,
        const float* __restrict__ W1, int ldw1, const float* __restrict__ u1,
        const float* __restrict__ W2, int ldw2, const float* __restrict__ u2,
        float* __restrict__ C, float* __restrict__ Hout) {
    const int tid = threadIdx.x, lane = tid & 31, warp = tid >> 5;
    const int h0 = blk * 4;
    int o[2]; unsigned long long acc2[2] = {0ull, 0ull};
    float base[2];
    #pragma unroll
    for (int rr = 0; rr < 2; rr++) {
        int r = warp * 2 + rr;
        o[rr] = (r >> 2) * H + h0 + (r & 3);
        base[rr] = zpre ? zpre[(size_t)o[rr] * B + lane] : bias[o[rr]];
    }
    #pragma unroll
    for (int m = 0; m < 2; m++) {
        const float* W = m ? W2 : W1;
        const float* u = m ? u2 : u1;
        const int ldw  = m ? ldw2 : ldw1;
        if (!W) continue;
        for (int k0 = 0; k0 < H; k0 += 128) {
            const float4* srcv = (const float4*)(u + (size_t)k0 * B);
            float4* dv = (float4*)su;
            #pragma unroll
            for (int i = tid; i < 128 * B / 4; i += 256) dv[i] = srcv[i];
            __syncthreads();
            #pragma unroll 8
            for (int kk = 0; kk < 128; kk += 4) {
                unsigned long long u01 = pack2(su[(kk+0)*B + lane], su[(kk+1)*B + lane]);
                unsigned long long u23 = pack2(su[(kk+2)*B + lane], su[(kk+3)*B + lane]);
                #pragma unroll
                for (int rr = 0; rr < 2; rr++) {
                    ulonglong2 w = *(const ulonglong2*)(W + (size_t)o[rr] * ldw + k0 + kk);
                    fma2(acc2[rr], w.x, u01);
                    fma2(acc2[rr], w.y, u23);
                }
            }
            __syncthreads();
        }
    }
    #pragma unroll
    for (int rr = 0; rr < 2; rr++)
        sz[(warp * 2 + rr) * B + lane] = base[rr] + sum2(acc2[rr]);
    __syncthreads();
    if (tid < 4 * B) {
        int j = tid >> 5, b = tid & 31;
        float zi = sz[(0*4 + j) * B + b];
        float zf = sz[(1*4 + j) * B + b];
        float zg = sz[(2*4 + j) * B + b];
        float zo = sz[(3*4 + j) * B + b];
        float ig = 1.f / (1.f + expf(-zi));
        float fg = 1.f / (1.f + expf(-zf));
        float gg = tanhf(zg);
        float og = 1.f / (1.f + expf(-zo));
        int h = h0 + j;
        float c  = C[h * B + b];
        float c2 = fg * c + ig * gg;
        C[h * B + b]    = c2;
        Hout[h * B + b] = og * tanhf(c2);
    }
}

// out[o,b] = tanh( W1[o,:].u1 (+ W2[o,:].u2) ). blocks 0..63, warp per row.
__device__ __forceinline__ void gemm8_tanh(
        int blk, float* su,
        const float* __restrict__ W1, int ldw1, const float* __restrict__ u1,
        const float* __restrict__ W2, int ldw2, const float* __restrict__ u2,
        float* __restrict__ outp) {
    const int tid = threadIdx.x, lane = tid & 31, warp = tid >> 5;
    const int o = blk * 8 + warp;
    unsigned long long acc2 = 0ull;
    #pragma unroll
    for (int m = 0; m < 2; m++) {
        const float* W = m ? W2 : W1;
        const float* u = m ? u2 : u1;
        const int ldw  = m ? ldw2 : ldw1;
        if (!W) continue;
        for (int k0 = 0; k0 < H; k0 += 128) {
            const float4* srcv = (const float4*)(u + (size_t)k0 * B);
            float4* dv = (float4*)su;
            #pragma unroll
            for (int i = tid; i < 128 * B / 4; i += 256) dv[i] = srcv[i];
            __syncthreads();
            #pragma unroll 8
            for (int kk = 0; kk < 128; kk += 4) {
                unsigned long long u01 = pack2(su[(kk+0)*B + lane], su[(kk+1)*B + lane]);
                unsigned long long u23 = pack2(su[(kk+2)*B + lane], su[(kk+3)*B + lane]);
                ulonglong2 w = *(const ulonglong2*)(W + (size_t)o * ldw + k0 + kk);
                fma2(acc2, w.x, u01);
                fma2(acc2, w.y, u23);
            }
            __syncthreads();
        }
    }
    outp[(size_t)o * B + lane] = tanhf(sum2(acc2));
}

// ---------------- persistent encoder: 128 sequential cells in ONE kernel ----
__global__ void __launch_bounds__(256) k_encoder(
        const float* __restrict__ eWhh0, const float* __restrict__ eWih1,
        const float* __restrict__ eWhh1, const float* __restrict__ eb1) {
    __shared__ __align__(16) float su[128 * B];
    __shared__ float sz[16 * B];
    const int blk = blockIdx.x, tid = threadIdx.x;
    for (int s = 0; s < S; s++) {
        const float* hp = s ? g_h1seq + (size_t)(s - 1) * H * B : g_zero;
        cell_chunk(blk, su, sz, g_zx0 + (size_t)s * H4 * B, nullptr,
                   eWhh0, H, hp, nullptr, 0, nullptr,
                   g_c0, g_h1seq + (size_t)s * H * B);
        gridbar();
    }
    for (int s = 0; s < S; s++) {
        const float* hp = s ? g_h2seq + (size_t)(s - 1) * H * B : g_zero;
        cell_chunk(blk, su, sz, nullptr, eb1,
                   eWih1, H, g_h1seq + (size_t)s * H * B,
                   eWhh1, H, hp,
                   g_c1, g_h2seq + (size_t)s * H * B);
        gridbar();
    }
    // transpose encode_h into [b,s,h] and [b,h,s]
    for (int idx = blk; idx < S * B; idx += NBLK) {
        int s = idx >> 5, b = idx & 31;
        for (int h = tid; h < H; h += 256) {
            float v = g_h2seq[((size_t)s * H + h) * B + b];
            g_ebsh[((size_t)b * S + s) * H + h] = v;
            g_ebhs[((size_t)b * H + h) * S + s] = v;
        }
    }
}

// ---------------- persistent decoder: 48 steps x 5 phases in ONE kernel ----
__global__ void __launch_bounds__(256) k_decoder(
        const float* __restrict__ dWih0, const float* __restrict__ dWhh0,
        const float* __restrict__ dWih1, const float* __restrict__ dWhh1,
        const float* __restrict__ db1,
        const float* __restrict__ Wht, const float* __restrict__ Wpt,
        const float* __restrict__ Wct, const int* __restrict__ elen) {
    __shared__ __align__(16) float su[128 * B];
    __shared__ float sz[16 * B];
    __shared__ float s_at[S];
    __shared__ float s_red[8];
    __shared__ float s_pt;
    const int blk = blockIdx.x, tid = threadIdx.x, lane = tid & 31, warp = tid >> 5;

    for (int t = 0; t < T; t++) {
        const float* htp = t ? g_decout + (size_t)(t - 1) * H * B : g_zero;
        const float* h0p = t ? (((t - 1) & 1) ? g_dh0b : g_dh0a)
                             : g_h1seq + (size_t)(S - 1) * H * B;
        float* h0c = (t & 1) ? g_dh0b : g_dh0a;
        // P1: decoder layer-0 cell
        cell_chunk(blk, su, sz, g_zy + (size_t)t * H4 * B, nullptr,
                   dWih0 + E, E + H, htp, dWhh0, H, h0p, g_c0, h0c);
        gridbar();
        // P2: decoder layer-1 cell
        const float* h1p = t ? (((t - 1) & 1) ? g_dh1b : g_dh1a)
                             : g_h2seq + (size_t)(S - 1) * H * B;
        float* h1c = (t & 1) ? g_dh1b : g_dh1a;
        cell_chunk(blk, su, sz, nullptr, db1,
                   dWih1, H, h0c, dWhh1, H, h1p, g_c1, h1c);
        gridbar();
        // P3: tmp = tanh(Wht.yt) on blocks 0..63; scores on blocks 64..95
        if (blk < 64) {
            gemm8_tanh(blk, su, Wht, H, h1c, nullptr, 0, nullptr, g_tmp);
        } else if (blk < 96) {
            int b = blk - 64;
            for (int h = tid; h < H; h += 256) su[h] = h1c[(size_t)h * B + b];
            __syncthreads();
            int el = elen[b];
            for (int s = warp; s < S; s += 8) {
                const float* eh = &g_ebsh[((size_t)b * S + s) * H];
                float v = 0.f;
                for (int h = lane; h < H; h += 32) v += su[h] * eh[h];
                #pragma unroll
                for (int off = 16; off; off >>= 1)
                    v += __shfl_xor_sync(0xffffffffu, v, off);
                if (lane == 0) g_scores[b * S + s] = (s < el) ? v : -INFINITY;
            }
        }
        gridbar();
        // P4: pt + softmax*gauss + ct on blocks 0..31 (one per batch)
        if (blk < B) {
            int b = blk;
            float p = 0.f;
            for (int h = tid; h < H; h += 256) p += g_tmp[(size_t)h * B + b] * Wpt[h];
            #pragma unroll
            for (int off = 16; off; off >>= 1) p += __shfl_xor_sync(0xffffffffu, p, off);
            if (lane == 0) s_red[warp] = p;
            __syncthreads();
            if (tid == 0) {
                float tt = 0.f;
                #pragma unroll
                for (int w = 0; w < 8; w++) tt += s_red[w];
                s_pt = (1.f / (1.f + expf(-tt))) * (float)elen[b];
            }
            __syncthreads();
            if (warp == 0) {
                float pt = s_pt;
                float v0 = g_scores[b * S + lane], v1 = g_scores[b * S + lane + 32];
                float m = fmaxf(v0, v1);
                #pragma unroll
                for (int off = 16; off; off >>= 1)
                    m = fmaxf(m, __shfl_xor_sync(0xffffffffu, m, off));
                float e0 = expf(v0 - m), e1 = expf(v1 - m);
                float sm = e0 + e1;
                #pragma unroll
                for (int off = 16; off; off >>= 1)
                    sm += __shfl_xor_sync(0xffffffffu, sm, off);
                float inv = 1.f / sm;
                float d0 = (float)lane - pt, d1 = (float)(lane + 32) - pt;
                s_at[lane]      = e0 * inv * expf(-d0 * d0 * (1.f / 50.f));
                s_at[lane + 32] = e1 * inv * expf(-d1 * d1 * (1.f / 50.f));
            }
            __syncthreads();
            for (int h = tid; h < H; h += 256) {
                const float4* eh = (const float4*)&g_ebhs[((size_t)b * H + h) * S];
                float v = 0.f;
                #pragma unroll
                for (int s4 = 0; s4 < 16; s4++) {
                    float4 e = eh[s4];
                    v += s_at[s4*4+0]*e.x + s_at[s4*4+1]*e.y
                       + s_at[s4*4+2]*e.z + s_at[s4*4+3]*e.w;
                }
                g_ct[(size_t)h * B + b] = v;
            }
        }
        gridbar();
        // P5: htn = tanh(Wct.[ct;yt]) on blocks 0..63
        if (blk < 64)
            gemm8_tanh(blk, su, Wct, 2 * H, g_ct, Wct + H, 2 * H, h1c,
                       g_decout + (size_t)t * H * B);
        gridbar();
    }
}

// vocab projection + online logsumexp partials + target-logit grab.
// grid (NCHUNK, TL), 256 thr, dynamic smem = 512*32*4 = 64KB decoder-state tile.
__global__ void __launch_bounds__(256) k_logits(const float* __restrict__ Wf,
                                                const int* __restrict__ target) {
    extern __shared__ __align__(16) float sdec[]; // [512][32]
    __shared__ float rm[8][32], rs[8][32];
    const int t = blockIdx.y, c = blockIdx.x;
    const int tid = threadIdx.x, lane = tid & 31, warp = tid >> 5;
    const float4* src = (const float4*)&g_decout[(size_t)t * H * B];
    float4* dv = (float4*)sdec;
    #pragma unroll
    for (int i = tid; i < H * B / 4; i += 256) dv[i] = src[i];
    __syncthreads();
    const int tgt = target[(t + 1) * B + lane];
    float m = -INFINITY, ss = 0.f;
    for (int pass = 0; pass < 10; pass++) {
        const int v0 = c * VB + warp * 80 + pass * 8;
        unsigned long long acc2[8] = {0ull,0ull,0ull,0ull,0ull,0ull,0ull,0ull};
        #pragma unroll 2
        for (int k0 = 0; k0 < H; k0 += 4) {
            unsigned long long u01 = pack2(sdec[(k0+0)*B + lane], sdec[(k0+1)*B + lane]);
            unsigned long long u23 = pack2(sdec[(k0+2)*B + lane], sdec[(k0+3)*B + lane]);
            #pragma unroll
            for (int r = 0; r < 8; r++) {
                ulonglong2 w = *(const ulonglong2*)(Wf + (size_t)(v0 + r) * H + k0);
                fma2(acc2[r], w.x, u01);
                fma2(acc2[r], w.y, u23);
            }
        }
        #pragma unroll
        for (int r = 0; r < 8; r++) {
            float x = sum2(acc2[r]);
            if (v0 + r == tgt) g_tgtl[t * B + lane] = x;
            float nm = fmaxf(m, x);
            ss = ss * expf(m - nm) + expf(x - nm);
            m = nm;
        }
    }
    rm[warp][lane] = m; rs[warp][lane] = ss;
    __syncthreads();
    if (tid < 32) {
        float M = -INFINITY, SS = 0.f;
        #pragma unroll
        for (int w = 0; w < 8; w++) {
            float wm = rm[w][tid], wss = rs[w][tid];
            float nm = fmaxf(M, wm);
            SS = SS * expf(M - nm) + wss * expf(wm - nm);
            M = nm;
        }
        g_pmax[((size_t)t * NCHUNK + c) * B + tid] = M;
        g_psum[((size_t)t * NCHUNK + c) * B + tid] = SS;
    }
}

__global__ void k_combine(const int* __restrict__ target) {
    const int t = blockIdx.x, b = threadIdx.x;
    float M = -INFINITY;
    for (int c = 0; c < NCHUNK; c++)
        M = fmaxf(M, g_pmax[((size_t)t * NCHUNK + c) * B + b]);
    float ss = 0.f;
    for (int c = 0; c < NCHUNK; c++)
        ss += g_psum[((size_t)t * NCHUNK + c) * B + b] *
              expf(g_pmax[((size_t)t * NCHUNK + c) * B + b] - M);
    float lse = M + logf(ss);
    float mask = (target[(t + 1) * B + b] != 0) ? 1.f : 0.f;
    g_lp[t * B + b] = mask * (g_tgtl[t * B + b] - lse);
}

__global__ void k_out(float* __restrict__ out) {
    const int b = threadIdx.x;
    float s = 0.f;
    for (int t = 0; t < TL; t++) s += g_lp[t * B + b];
    out[b] = s;
}

// ---------------- host ----------------
extern "C" void kernel_launch(void* const* d_in, const int* in_sizes, int n_in,
                              void* d_out, int out_size) {
    const int*   source   = (const int*)d_in[0];
    const int*   target   = (const int*)d_in[1];
    const int*   elen     = (const int*)d_in[2];
    const float* src_emb  = (const float*)d_in[3];
    const float* tar_emb  = (const float*)d_in[4];
    const float* eWih0    = (const float*)d_in[5];
    const float* eWhh0    = (const float*)d_in[6];
    const float* eb0      = (const float*)d_in[7];
    const float* eWih1    = (const float*)d_in[8];
    const float* eWhh1    = (const float*)d_in[9];
    const float* eb1      = (const float*)d_in[10];
    const float* dWih0    = (const float*)d_in[11];
    const float* dWhh0    = (const float*)d_in[12];
    const float* db0      = (const float*)d_in[13];
    const float* dWih1    = (const float*)d_in[14];
    const float* dWhh1    = (const float*)d_in[15];
    const float* db1      = (const float*)d_in[16];
    const float* W_ht2tan = (const float*)d_in[17];
    const float* W_tan2pt = (const float*)d_in[18];
    const float* W_ct2ht  = (const float*)d_in[19];
    const float* W_final  = (const float*)d_in[20];
    float* out = (float*)d_out;

    float *x, *y, *zx0, *zy, *c0, *c1, *zerop;
    cudaGetSymbolAddress((void**)&x, g_x);
    cudaGetSymbolAddress((void**)&y, g_y);
    cudaGetSymbolAddress((void**)&zx0, g_zx0);
    cudaGetSymbolAddress((void**)&zy, g_zy);
    cudaGetSymbolAddress((void**)&c0, g_c0);
    cudaGetSymbolAddress((void**)&c1, g_c1);
    cudaGetSymbolAddress((void**)&zerop, g_zero);

    cudaFuncSetAttribute(k_logits, cudaFuncAttributeMaxDynamicSharedMemorySize, 65536);

    const int nzb = (H * B + 255) / 256;
    k_zero<<<nzb, 256>>>(zerop, H * B);
    k_zero<<<nzb, 256>>>(c0, H * B);
    k_zero<<<nzb, 256>>>(c1, H * B);

    k_embed<<<dim3(S, B), 128>>>(source, src_emb, x);
    k_embed<<<dim3(T, B), 128>>>(target, tar_emb, y);

    // precompute time-parallel input GEMMs
    k_gemm_pre<<<dim3(32, S), 256>>>(eWih0, E, eb0, x, zx0);
    k_gemm_pre<<<dim3(32, T), 256>>>(dWih0, E + H, db0, y, zy);

    // persistent encoder (both layers + transpose, 128 grid barriers inside)
    k_encoder<<<NBLK, 256>>>(eWhh0, eWih1, eWhh1, eb1);

    // persistent decoder (48 steps x 5 phases, grid barriers inside)
    k_decoder<<<NBLK, 256>>>(dWih0, dWhh0, dWih1, dWhh1, db1,
                             W_ht2tan, W_tan2pt, W_ct2ht, elen);

    k_logits<<<dim3(NCHUNK, TL), 256, 65536>>>(W_final, target);
    k_combine<<<TL, 32>>>(target);
    k_out<<<1, 32>>>(out);
}